// round 9
// baseline (speedup 1.0000x reference)
#include <cuda_runtime.h>
#include <cstdint>

// Per-token int4 quantization — two rows per CTA, pipelined:
//   x: [N, H] fp32 (H = 4096)
//   scales[n] = max|x[n,:]| / 7
//   q = rint(x * 7/max)   (in [-7,7] by construction; clamp-free)
//   packed byte = ((q_odd & 0xF) << 4) | (q_even & 0xF)  (signed int8 value)
//
// Each CTA handles rows {2b, 2b+1}: 8 front-batched LDG.128/thread, ONE
// barrier serving both rows' max-reductions, then both epilogues from
// registers. Amortizes the reduce+barrier bubble across 2x memory work.
//
// Cache policy: loads __ldcs (streaming input, read once); stores default
// write-back (graph replays overwrite d_out; L2-resident dirty lines never
// cost DRAM write bandwidth — measured -47MB DRAM traffic in R8).
//
// Harness output layout (detected via out_size):
//   FLOAT_OUT: [N*H/2 float32 (packed byte values)][N float32 scales]
//   BYTE_OUT : [N*H/2 int8][N float32 scales]

constexpr int H       = 4096;
constexpr int THREADS = 256;
constexpr int CHUNKS  = H / 4 / THREADS;  // 4 float4-chunks per thread per row

template <bool FLOAT_OUT>
__global__ __launch_bounds__(THREADS, 4)
void quant_int4_kernel(const float* __restrict__ x,
                       void* __restrict__ packed_out,
                       float* __restrict__ scales)
{
    const int rowA = 2 * blockIdx.x;
    const int rowB = rowA + 1;
    const int t    = threadIdx.x;

    const float4* xa = reinterpret_cast<const float4*>(x + (size_t)rowA * H);
    const float4* xb = reinterpret_cast<const float4*>(x + (size_t)rowB * H);

    // Front-batch all 8 streaming loads (MLP=8 per thread).
    float4 va[CHUNKS], vb[CHUNKS];
#pragma unroll
    for (int k = 0; k < CHUNKS; ++k) va[k] = __ldcs(&xa[t + THREADS * k]);
#pragma unroll
    for (int k = 0; k < CHUNKS; ++k) vb[k] = __ldcs(&xb[t + THREADS * k]);

    // Local max|x| for both rows.
    float ma = 0.0f, mb = 0.0f;
#pragma unroll
    for (int k = 0; k < CHUNKS; ++k) {
        ma = fmaxf(ma, fmaxf(fmaxf(fabsf(va[k].x), fabsf(va[k].y)),
                             fmaxf(fabsf(va[k].z), fabsf(va[k].w))));
        mb = fmaxf(mb, fmaxf(fmaxf(fabsf(vb[k].x), fabsf(vb[k].y)),
                             fmaxf(fabsf(vb[k].z), fabsf(vb[k].w))));
    }

    // Warp reduce both (independent shuffle chains — dual-issue friendly).
#pragma unroll
    for (int o = 16; o > 0; o >>= 1) {
        ma = fmaxf(ma, __shfl_xor_sync(0xffffffffu, ma, o));
        mb = fmaxf(mb, __shfl_xor_sync(0xffffffffu, mb, o));
    }

    __shared__ float smaxA[THREADS / 32];
    __shared__ float smaxB[THREADS / 32];
    if ((t & 31) == 0) { smaxA[t >> 5] = ma; smaxB[t >> 5] = mb; }
    __syncthreads();   // ONE barrier for both rows

    float rmaxA = smaxA[0], rmaxB = smaxB[0];
#pragma unroll
    for (int w = 1; w < THREADS / 32; ++w) {
        rmaxA = fmaxf(rmaxA, smaxA[w]);
        rmaxB = fmaxf(rmaxB, smaxB[w]);
    }

    const float invA = (rmaxA > 0.0f) ? 7.0f / rmaxA : 0.0f;
    const float invB = (rmaxB > 0.0f) ? 7.0f / rmaxB : 0.0f;

    if (t == 0) scales[rowA] = rmaxA / 7.0f;
    if (t == 1) scales[rowB] = rmaxB / 7.0f;

    if (FLOAT_OUT) {
        float2* opA = reinterpret_cast<float2*>((float*)packed_out + (size_t)rowA * (H / 2));
        float2* opB = reinterpret_cast<float2*>((float*)packed_out + (size_t)rowB * (H / 2));
#pragma unroll
        for (int k = 0; k < CHUNKS; ++k) {
            float q0 = rintf(va[k].x * invA);
            float q1 = rintf(va[k].y * invA);
            float q2 = rintf(va[k].z * invA);
            float q3 = rintf(va[k].w * invA);
            float n0 = q0 + (q0 < 0.0f ? 16.0f : 0.0f);
            float n2 = q2 + (q2 < 0.0f ? 16.0f : 0.0f);
            opA[t + THREADS * k] = make_float2(fmaf(16.0f, q1, n0),
                                               fmaf(16.0f, q3, n2));
        }
#pragma unroll
        for (int k = 0; k < CHUNKS; ++k) {
            float q0 = rintf(vb[k].x * invB);
            float q1 = rintf(vb[k].y * invB);
            float q2 = rintf(vb[k].z * invB);
            float q3 = rintf(vb[k].w * invB);
            float n0 = q0 + (q0 < 0.0f ? 16.0f : 0.0f);
            float n2 = q2 + (q2 < 0.0f ? 16.0f : 0.0f);
            opB[t + THREADS * k] = make_float2(fmaf(16.0f, q1, n0),
                                               fmaf(16.0f, q3, n2));
        }
    } else {
        uint16_t* opA = reinterpret_cast<uint16_t*>((int8_t*)packed_out + (size_t)rowA * (H / 2));
        uint16_t* opB = reinterpret_cast<uint16_t*>((int8_t*)packed_out + (size_t)rowB * (H / 2));
#pragma unroll
        for (int k = 0; k < CHUNKS; ++k) {
            int q0 = __float2int_rn(va[k].x * invA);
            int q1 = __float2int_rn(va[k].y * invA);
            int q2 = __float2int_rn(va[k].z * invA);
            int q3 = __float2int_rn(va[k].w * invA);
            opA[t + THREADS * k] = (uint16_t)((((q3 & 0xF) << 4) | (q2 & 0xF)) << 8
                                            | (((q1 & 0xF) << 4) | (q0 & 0xF)));
        }
#pragma unroll
        for (int k = 0; k < CHUNKS; ++k) {
            int q0 = __float2int_rn(vb[k].x * invB);
            int q1 = __float2int_rn(vb[k].y * invB);
            int q2 = __float2int_rn(vb[k].z * invB);
            int q3 = __float2int_rn(vb[k].w * invB);
            opB[t + THREADS * k] = (uint16_t)((((q3 & 0xF) << 4) | (q2 & 0xF)) << 8
                                            | (((q1 & 0xF) << 4) | (q0 & 0xF)));
        }
    }
}

extern "C" void kernel_launch(void* const* d_in, const int* in_sizes, int n_in,
                              void* d_out, int out_size)
{
    const float* x = (const float*)d_in[0];
    const int rows = in_sizes[0] / H;   // 8192 (even)
    const long long packed_elems = (long long)rows * (H / 2);

    if ((long long)out_size == packed_elems + rows) {
        float* packed = (float*)d_out;
        float* scales = packed + packed_elems;
        quant_int4_kernel<true><<<rows / 2, THREADS>>>(x, packed, scales);
    } else {
        int8_t* packed = (int8_t*)d_out;
        float*  scales = (float*)(packed + packed_elems);
        quant_int4_kernel<false><<<rows / 2, THREADS>>>(x, packed, scales);
    }
}